// round 10
// baseline (speedup 1.0000x reference)
#include <cuda_runtime.h>

// WeightedAggregator: out[b,:] = sum_k (w[b,k]/sum_j w[b,j]) * features[idx[b,k],:]
// B = 50000, K = 16, D = 128 (fp32). One warp per output row; one float4 per lane.
// neigh_idx is int32 (JAX demotes int64 without x64 mode).
//
// R10: persistent single-wave grid. 888 CTAs (148 SMs x 6 resident CTAs at
// 38 regs), each warp grid-strides over rows (7-8 rows/warp). Removes the
// ~7 wave transitions + tail-wave imbalance of the 6250-CTA launch, and lets
// the next row's index/weight loads pipeline behind the current row's FMAs.

#define K_NEIGH 16
#define FEAT_D 128

__device__ __forceinline__ float4 ldg_nc_v4(const float4* p) {
    float4 v;
    asm("ld.global.nc.v4.f32 {%0,%1,%2,%3}, [%4];"
        : "=f"(v.x), "=f"(v.y), "=f"(v.z), "=f"(v.w)
        : "l"(p));
    return v;
}

__global__ __launch_bounds__(256)
void weighted_agg_kernel(const float* __restrict__ features,
                         const float* __restrict__ neigh_w,
                         const int* __restrict__ neigh_idx,
                         float* __restrict__ out,
                         int B)
{
    const int lane       = threadIdx.x & 31;
    const int warp_id    = (blockIdx.x * blockDim.x + threadIdx.x) >> 5;
    const int warp_count = (gridDim.x * blockDim.x) >> 5;

    const float4* __restrict__ feat4 = (const float4*)features;

    for (int row = warp_id; row < B; row += warp_count) {
        // Lanes 0..15 hold this row's weight + index; others hold 0.
        float w  = 0.0f;
        int   ix = 0;
        if (lane < K_NEIGH) {
            w  = neigh_w  [row * K_NEIGH + lane];
            ix = neigh_idx[row * K_NEIGH + lane];
        }

        // Warp-wide weight sum (lanes >= 16 contribute 0).
        float s = w;
        #pragma unroll
        for (int off = 16; off > 0; off >>= 1)
            s += __shfl_xor_sync(0xffffffffu, s, off);
        const float inv = 1.0f / s;

        float4 a0 = make_float4(0.f, 0.f, 0.f, 0.f);
        float4 a1 = make_float4(0.f, 0.f, 0.f, 0.f);

        // 4 groups of 4 gathers; asm loads stay front-batched per group.
        #pragma unroll
        for (int g = 0; g < K_NEIGH; g += 4) {
            const int i0 = __shfl_sync(0xffffffffu, ix, g + 0);
            const int i1 = __shfl_sync(0xffffffffu, ix, g + 1);
            const int i2 = __shfl_sync(0xffffffffu, ix, g + 2);
            const int i3 = __shfl_sync(0xffffffffu, ix, g + 3);

            const float4 f0 = ldg_nc_v4(feat4 + (long long)i0 * (FEAT_D / 4) + lane);
            const float4 f1 = ldg_nc_v4(feat4 + (long long)i1 * (FEAT_D / 4) + lane);
            const float4 f2 = ldg_nc_v4(feat4 + (long long)i2 * (FEAT_D / 4) + lane);
            const float4 f3 = ldg_nc_v4(feat4 + (long long)i3 * (FEAT_D / 4) + lane);

            const float w0 = __shfl_sync(0xffffffffu, w, g + 0);
            const float w1 = __shfl_sync(0xffffffffu, w, g + 1);
            const float w2 = __shfl_sync(0xffffffffu, w, g + 2);
            const float w3 = __shfl_sync(0xffffffffu, w, g + 3);

            a0.x += w0 * f0.x;  a0.y += w0 * f0.y;  a0.z += w0 * f0.z;  a0.w += w0 * f0.w;
            a1.x += w1 * f1.x;  a1.y += w1 * f1.y;  a1.z += w1 * f1.z;  a1.w += w1 * f1.w;
            a0.x += w2 * f2.x;  a0.y += w2 * f2.y;  a0.z += w2 * f2.z;  a0.w += w2 * f2.w;
            a1.x += w3 * f3.x;  a1.y += w3 * f3.y;  a1.z += w3 * f3.z;  a1.w += w3 * f3.w;
        }

        float4 r;
        r.x = (a0.x + a1.x) * inv;
        r.y = (a0.y + a1.y) * inv;
        r.z = (a0.z + a1.z) * inv;
        r.w = (a0.w + a1.w) * inv;

        ((float4*)out)[(long long)row * (FEAT_D / 4) + lane] = r;
    }
}

extern "C" void kernel_launch(void* const* d_in, const int* in_sizes, int n_in,
                              void* d_out, int out_size)
{
    const float* features  = (const float*)d_in[0];   // [N_NODES, 128] fp32
    const float* neigh_w   = (const float*)d_in[1];   // [B, 16] fp32
    const int*   neigh_idx = (const int*)d_in[2];     // [B, 16] int32
    float*       out       = (float*)d_out;           // [B, 128] fp32

    const int B = in_sizes[1] / K_NEIGH;   // 50000

    // Single-wave persistent grid: 148 SMs x 6 resident CTAs (38 regs x 256
    // threads x 6 = 58K regs < 64K). Each warp handles ceil(50000/7104) rows.
    const int threads = 256;
    const int blocks  = 148 * 6;

    weighted_agg_kernel<<<blocks, threads>>>(features, neigh_w, neigh_idx, out, B);
}

// round 11
// speedup vs baseline: 1.2333x; 1.2333x over previous
#include <cuda_runtime.h>

// WeightedAggregator: out[b,:] = sum_k (w[b,k]/sum_j w[b,j]) * features[idx[b,k],:]
// B = 50000, K = 16, D = 128 (fp32). One warp per output row; one float4 per lane.
// neigh_idx is int32 (JAX demotes int64 without x64 mode).
//
// R11: best-known flat shape (R4/R9) with 128-thread CTAs. At 34 regs this
// admits 15 CTAs/SM = 60 resident warps (94% occ) vs 48 with 256-thr CTAs,
// deepening the per-SM memory queue and shrinking tail-wave imbalance
// (12500 fine-grained CTAs). Kernel body unchanged from the 53.8us version.

#define K_NEIGH 16
#define FEAT_D 128

__global__ __launch_bounds__(128)
void weighted_agg_kernel(const float* __restrict__ features,
                         const float* __restrict__ neigh_w,
                         const int* __restrict__ neigh_idx,
                         float* __restrict__ out,
                         int B)
{
    const int gtid = blockIdx.x * blockDim.x + threadIdx.x;
    const int row  = gtid >> 5;          // warp id = output row
    const int lane = threadIdx.x & 31;
    if (row >= B) return;

    // Lanes 0..15 hold this row's weight + index; others hold 0.
    float w  = 0.0f;
    int   ix = 0;
    if (lane < K_NEIGH) {
        w  = neigh_w  [row * K_NEIGH + lane];
        ix = neigh_idx[row * K_NEIGH + lane];
    }

    // Warp-wide weight sum (lanes >= 16 contribute 0).
    float s = w;
    #pragma unroll
    for (int off = 16; off > 0; off >>= 1)
        s += __shfl_xor_sync(0xffffffffu, s, off);
    const float inv = 1.0f / s;

    const float4* __restrict__ feat4 = (const float4*)features;

    // Gather + accumulate; ptxas schedules the loads (34-reg version measured
    // identical to the forced-MLP asm variant, so keep the cheaper form).
    float4 f[K_NEIGH];
    #pragma unroll
    for (int k = 0; k < K_NEIGH; k++) {
        const int ik = __shfl_sync(0xffffffffu, ix, k);
        f[k] = __ldg(feat4 + (long long)ik * (FEAT_D / 4) + lane);
    }

    float4 a0 = make_float4(0.f, 0.f, 0.f, 0.f);
    float4 a1 = make_float4(0.f, 0.f, 0.f, 0.f);
    #pragma unroll
    for (int k = 0; k < K_NEIGH; k += 2) {
        const float w0 = __shfl_sync(0xffffffffu, w, k);
        const float w1 = __shfl_sync(0xffffffffu, w, k + 1);
        a0.x += w0 * f[k].x;     a1.x += w1 * f[k + 1].x;
        a0.y += w0 * f[k].y;     a1.y += w1 * f[k + 1].y;
        a0.z += w0 * f[k].z;     a1.z += w1 * f[k + 1].z;
        a0.w += w0 * f[k].w;     a1.w += w1 * f[k + 1].w;
    }

    float4 r;
    r.x = (a0.x + a1.x) * inv;
    r.y = (a0.y + a1.y) * inv;
    r.z = (a0.z + a1.z) * inv;
    r.w = (a0.w + a1.w) * inv;

    ((float4*)out)[(long long)row * (FEAT_D / 4) + lane] = r;
}

extern "C" void kernel_launch(void* const* d_in, const int* in_sizes, int n_in,
                              void* d_out, int out_size)
{
    const float* features  = (const float*)d_in[0];   // [N_NODES, 128] fp32
    const float* neigh_w   = (const float*)d_in[1];   // [B, 16] fp32
    const int*   neigh_idx = (const int*)d_in[2];     // [B, 16] int32
    float*       out       = (float*)d_out;           // [B, 128] fp32

    const int B = in_sizes[1] / K_NEIGH;   // 50000

    const int threads = 128;               // 4 warps/block -> 4 rows/block
    const int rows_per_block = threads / 32;
    const int blocks = (B + rows_per_block - 1) / rows_per_block;   // 12500

    weighted_agg_kernel<<<blocks, threads>>>(features, neigh_w, neigh_idx, out, B);
}